// round 1
// baseline (speedup 1.0000x reference)
#include <cuda_runtime.h>

#define N_NODES 50000
#define IN_C   16
#define OUT_C  16
#define EDGE_F 13
#define HID    32
#define E_MAX  800000     // degs construction guarantees E <= 800000
#define TB     64         // edges per chunk
#define THREADS 256

// Scratch: per-edge prod vectors (51.2 MB). Static device array (no allocs allowed).
__device__ float g_prod[E_MAX * OUT_C];

// ---------------------------------------------------------------------------
// Phase 1: per-edge  prod[e, o] = sum_i x[idxn[e], i] * (h[e] @ W2 + b2)[i,o]
// Structured as: build H chunk (64x32) in smem, GEMM Wc = H @ W2 (64x256) in
// registers (thread owns 4 edges x 16 i-slots for one fixed o), then fold sel.
// ---------------------------------------------------------------------------
__global__ void __launch_bounds__(THREADS)
phase1_kernel(const float* __restrict__ x,
              const float* __restrict__ ef,
              const float* __restrict__ W1,
              const float* __restrict__ b1,
              const float* __restrict__ W2,
              const float* __restrict__ b2,
              const int*   __restrict__ idxn,
              int E, int nChunks)
{
    __shared__ float W2s[HID][IN_C * OUT_C];   // 32 KB, [j][i*16+o]
    __shared__ float W1s[EDGE_F][HID];
    __shared__ float b1s[HID];
    __shared__ float b2s[IN_C * OUT_C];
    __shared__ float HsT[HID][TB];             // h transposed: [j][t]
    __shared__ float SELs[TB][IN_C];
    __shared__ float EFs[TB][EDGE_F + 1];      // pad to 14 (bank spread)

    const int tid = threadIdx.x;

    // Load constants once per block
    for (int k = tid; k < HID * IN_C * OUT_C; k += THREADS)
        W2s[k >> 8][k & 255] = W2[k];
    for (int k = tid; k < EDGE_F * HID; k += THREADS)
        W1s[k / HID][k % HID] = W1[k];
    if (tid < HID) b1s[tid] = b1[tid];
    b2s[tid] = b2[tid];   // THREADS == 256 == IN_C*OUT_C
    __syncthreads();

    const int a = tid >> 4;   // edge-group (4 edges each)
    const int o = tid & 15;   // output column

    // Hoist this thread's b2 column into registers
    float b2r[16];
    #pragma unroll
    for (int i = 0; i < 16; i++) b2r[i] = b2s[i * 16 + o];

    for (int ch = blockIdx.x; ch < nChunks; ch += gridDim.x) {
        const int e_base = ch * TB;

        // --- stage edgefeats (linear, fully coalesced) ---
        for (int k = tid; k < TB * EDGE_F; k += THREADS) {
            int gi = e_base * EDGE_F + k;
            EFs[k / EDGE_F][k % EDGE_F] = (gi < E * EDGE_F) ? ef[gi] : 0.f;
        }
        // --- stage sel = x[idxn[e]] (gather, x is L2-resident) ---
        {
            int tl = tid >> 2, q = tid & 3;
            int e  = e_base + tl;
            int src = (e < E) ? idxn[e] : 0;
            ((float4*)&SELs[tl][0])[q] = ((const float4*)x)[src * 4 + q];
        }
        __syncthreads();

        // --- compute H chunk: h[t,j] = relu(ef[t] @ W1[:,j] + b1[j]) ---
        for (int k = tid; k < TB * HID; k += THREADS) {
            int tl = k & (TB - 1);
            int j  = k >> 6;           // TB == 64
            float h = b1s[j];
            #pragma unroll
            for (int f = 0; f < EDGE_F; f++)
                h = fmaf(EFs[tl][f], W1s[f][j], h);
            HsT[j][tl] = fmaxf(h, 0.f);
        }
        __syncthreads();

        // --- GEMM: acc[tt][i] = sum_j h[a*4+tt, j] * W2[j, i*16+o] ---
        float acc[4][16];
        #pragma unroll
        for (int tt = 0; tt < 4; tt++)
            #pragma unroll
            for (int i = 0; i < 16; i++) acc[tt][i] = 0.f;

        #pragma unroll 4
        for (int j = 0; j < HID; j++) {
            float4 h4 = *(const float4*)&HsT[j][a * 4];
            #pragma unroll
            for (int i = 0; i < 16; i++) {
                float w = W2s[j][i * 16 + o];   // conflict-free: lanes sweep banks
                acc[0][i] = fmaf(h4.x, w, acc[0][i]);
                acc[1][i] = fmaf(h4.y, w, acc[1][i]);
                acc[2][i] = fmaf(h4.z, w, acc[2][i]);
                acc[3][i] = fmaf(h4.w, w, acc[3][i]);
            }
        }

        // --- epilogue: prod[t][o] = sum_i sel[t][i] * (acc[tt][i] + b2[i,o]) ---
        #pragma unroll
        for (int tt = 0; tt < 4; tt++) {
            int tl = a * 4 + tt;
            int e  = e_base + tl;
            if (e < E) {
                float s = 0.f;
                #pragma unroll
                for (int i = 0; i < 16; i++)
                    s = fmaf(SELs[tl][i], acc[tt][i] + b2r[i], s);
                g_prod[e * 16 + o] = s;   // lanes o=0..15 -> 64B coalesced
            }
        }
        __syncthreads();
    }
}

// ---------------------------------------------------------------------------
// Phase 2: segment mean. idxd is sorted, so node n's edges are contiguous.
// One warp per node: lane 0 binary-searches the start, then halves of the
// warp sum alternating rows of g_prod (coalesced 128B reads).
// ---------------------------------------------------------------------------
__global__ void __launch_bounds__(256)
phase2_kernel(const float* __restrict__ degs,
              const int*   __restrict__ idxd,
              float* __restrict__ out,
              int E)
{
    int warp = (blockIdx.x * blockDim.x + threadIdx.x) >> 5;
    int lane = threadIdx.x & 31;
    if (warp >= N_NODES) return;
    const int n = warp;

    int deg = (int)degs[n];
    int o = lane & 15, half = lane >> 4;

    if (deg <= 0) {
        if (half == 0) out[n * 16 + o] = 0.f;
        return;
    }

    int start = 0;
    if (lane == 0) {
        int lo = 0, hi = E;
        while (lo < hi) {
            int mid = (lo + hi) >> 1;
            if (idxd[mid] < n) lo = mid + 1; else hi = mid;
        }
        start = lo;
    }
    start = __shfl_sync(0xffffffffu, start, 0);

    float acc = 0.f;
    for (int r = half; r < deg; r += 2)
        acc += g_prod[(start + r) * 16 + o];
    acc += __shfl_xor_sync(0xffffffffu, acc, 16);

    if (half == 0) out[n * 16 + o] = acc / (float)deg;
}

// ---------------------------------------------------------------------------
extern "C" void kernel_launch(void* const* d_in, const int* in_sizes, int n_in,
                              void* d_out, int out_size)
{
    const float* x   = (const float*)d_in[0];   // [N, 16]
    const float* ef  = (const float*)d_in[1];   // [E, 13]
    const float* W1  = (const float*)d_in[2];   // [13, 32]
    const float* b1  = (const float*)d_in[3];   // [32]
    const float* W2  = (const float*)d_in[4];   // [32, 256]
    const float* b2  = (const float*)d_in[5];   // [256]
    const int*   idxn = (const int*)d_in[6];    // [E]
    const int*   idxd = (const int*)d_in[7];    // [E]
    const float* degs = (const float*)d_in[8];  // [N]
    float* out = (float*)d_out;                 // [N, 16]

    const int E = in_sizes[6];
    const int nChunks = (E + TB - 1) / TB;

    phase1_kernel<<<592, THREADS>>>(x, ef, W1, b1, W2, b2, idxn, E, nChunks);

    const int warps_total = N_NODES;
    const int blocks2 = (warps_total * 32 + 255) / 256;
    phase2_kernel<<<blocks2, 256>>>(degs, idxd, out, E);
}

// round 2
// speedup vs baseline: 1.2927x; 1.2927x over previous
#include <cuda_runtime.h>

#define N_NODES 50000
#define IN_C   16
#define OUT_C  16
#define EDGE_F 13
#define HID    32
#define TB     64         // edges per chunk
#define THREADS 256

typedef unsigned long long ull;

// ---- packed fp32x2 helpers (sm_103a FFMA2 path, PTX-only) ----
__device__ __forceinline__ ull pk2(float a, float b) {
    ull r; asm("mov.b64 %0, {%1,%2};" : "=l"(r) : "f"(a), "f"(b)); return r;
}
__device__ __forceinline__ ull ffma2(ull a, ull b, ull c) {
    ull d; asm("fma.rn.f32x2 %0, %1, %2, %3;" : "=l"(d) : "l"(a), "l"(b), "l"(c)); return d;
}
__device__ __forceinline__ ull add2(ull a, ull b) {
    ull d; asm("add.rn.f32x2 %0, %1, %2;" : "=l"(d) : "l"(a), "l"(b)); return d;
}
__device__ __forceinline__ float2 unpk(ull a) {
    float2 f; asm("mov.b64 {%0,%1}, %2;" : "=f"(f.x), "=f"(f.y) : "l"(a)); return f;
}

// ---------------------------------------------------------------------------
// zero out
// ---------------------------------------------------------------------------
__global__ void zero_kernel(float4* out4, int n4)
{
    int i = blockIdx.x * blockDim.x + threadIdx.x;
    if (i < n4) out4[i] = make_float4(0.f, 0.f, 0.f, 0.f);
}

// ---------------------------------------------------------------------------
// Phase 1 (fused): per-edge prod, scattered via RED.ADD into out (unnormalized)
// GEMM acc layout: thread (a = tid>>4 owns 4 edges, o = tid&15 owns column o),
// acc[edge][pair-of-i] held as packed fp32x2; FFMA2 halves issue count.
// W2 stored in smem with XOR bank-swizzle so packed LDS.64 is conflict-free.
// ---------------------------------------------------------------------------
__global__ void __launch_bounds__(THREADS, 2)
phase1_kernel(const float* __restrict__ x,
              const float* __restrict__ ef,
              const float* __restrict__ W1,
              const float* __restrict__ b1,
              const float* __restrict__ W2,
              const float* __restrict__ b2,
              const int*   __restrict__ idxn,
              const int*   __restrict__ idxd,
              float* __restrict__ out,
              int E, int nChunks)
{
    __shared__ __align__(16) float W2q[HID * 256];      // 32 KB, swizzled pairs
    __shared__ float W1s[EDGE_F][HID];                  // 1.6 KB
    __shared__ float b1s[HID];
    __shared__ __align__(16) float HsT[HID][TB];        // 8 KB  [j][t]
    __shared__ float EFs[TB][EDGE_F];                   // 3.25 KB

    const int tid = threadIdx.x;
    const int a  = tid >> 4;        // edge group (4 edges)
    const int o  = tid & 15;        // output column
    const int sw = o + (o >> 3);    // swizzle key

    // ---- load constants (once per block) ----
    // W2 global layout [j][i*16+o]; store pair (i=2p,2p+1) for column o at
    // slot s = (p + o + (o>>3)) & 7  ->  W2q[j*256 + o*16 + 2s + (i&1)]
    for (int k = tid; k < HID * 256; k += THREADS) {
        int j = k >> 8, rem = k & 255;
        int i = rem >> 4, oc = rem & 15;
        int s = ((i >> 1) + oc + (oc >> 3)) & 7;
        W2q[j * 256 + oc * 16 + 2 * s + (i & 1)] = W2[k];
    }
    for (int k = tid; k < EDGE_F * HID; k += THREADS)
        W1s[k / HID][k % HID] = W1[k];
    if (tid < HID) b1s[tid] = b1[tid];
    __syncthreads();

    // b2 column for this thread's o, as packed pairs
    ull b2r2[8];
    #pragma unroll
    for (int p = 0; p < 8; p++)
        b2r2[p] = pk2(__ldg(b2 + (2 * p) * 16 + o), __ldg(b2 + (2 * p + 1) * 16 + o));

    for (int ch = blockIdx.x; ch < nChunks; ch += gridDim.x) {
        const int e_base = ch * TB;

        // ---- stage edgefeats (coalesced) ----
        for (int k = tid; k < TB * EDGE_F; k += THREADS) {
            int gi = e_base * EDGE_F + k;
            EFs[k / EDGE_F][k % EDGE_F] = (gi < E * EDGE_F) ? ef[gi] : 0.f;
        }
        __syncthreads();

        // ---- H chunk: h[t,j] = relu(ef[t] @ W1[:,j] + b1[j]) ----
        for (int k = tid; k < TB * HID; k += THREADS) {
            int tl = k & (TB - 1);
            int j  = k >> 6;
            float h = b1s[j];
            #pragma unroll
            for (int f = 0; f < EDGE_F; f++)
                h = fmaf(EFs[tl][f], W1s[f][j], h);
            HsT[j][tl] = fmaxf(h, 0.f);
        }
        __syncthreads();

        // ---- GEMM: acc[tt][p] (+)= h[a*4+tt, j] * W2pair[j, 2p..2p+1, o] ----
        ull acc[4][8];
        #pragma unroll
        for (int tt = 0; tt < 4; tt++)
            #pragma unroll
            for (int p = 0; p < 8; p++) acc[tt][p] = 0ULL;

        #pragma unroll 4
        for (int j = 0; j < HID; j++) {
            float4 h4 = *(const float4*)&HsT[j][a * 4];
            ull ha = pk2(h4.x, h4.x);
            ull hb = pk2(h4.y, h4.y);
            ull hc = pk2(h4.z, h4.z);
            ull hd = pk2(h4.w, h4.w);
            const ull* wrow = (const ull*)&W2q[j * 256 + o * 16];
            #pragma unroll
            for (int p = 0; p < 8; p++) {
                ull w2 = wrow[(p + sw) & 7];   // conflict-free LDS.64
                acc[0][p] = ffma2(ha, w2, acc[0][p]);
                acc[1][p] = ffma2(hb, w2, acc[1][p]);
                acc[2][p] = ffma2(hc, w2, acc[2][p]);
                acc[3][p] = ffma2(hd, w2, acc[3][p]);
            }
        }

        // ---- epilogue: s = sel . (acc + b2), combine same-dest, RED to out ----
        const int a4 = e_base + a * 4;
        if (a4 < E) {
            int nn[4], dd[4];
            if (a4 + 3 < E) {
                int4 t = *(const int4*)(idxn + a4);
                int4 u = *(const int4*)(idxd + a4);
                nn[0] = t.x; nn[1] = t.y; nn[2] = t.z; nn[3] = t.w;
                dd[0] = u.x; dd[1] = u.y; dd[2] = u.z; dd[3] = u.w;
            } else {
                #pragma unroll
                for (int tt = 0; tt < 4; tt++) {
                    int e = a4 + tt;
                    nn[tt] = (e < E) ? idxn[e] : 0;
                    dd[tt] = (e < E) ? idxd[e] : -1;
                }
            }
            int curd = -1; float cur = 0.f;
            #pragma unroll
            for (int tt = 0; tt < 4; tt++) {
                int e = a4 + tt;
                if (e < E) {
                    const float4* xp = (const float4*)(x + (size_t)nn[tt] * 16);
                    float selv[16];
                    *(float4*)&selv[0]  = __ldg(xp + 0);
                    *(float4*)&selv[4]  = __ldg(xp + 1);
                    *(float4*)&selv[8]  = __ldg(xp + 2);
                    *(float4*)&selv[12] = __ldg(xp + 3);
                    ull s2 = 0ULL;
                    #pragma unroll
                    for (int p = 0; p < 8; p++)
                        s2 = ffma2(pk2(selv[2 * p], selv[2 * p + 1]),
                                   add2(acc[tt][p], b2r2[p]), s2);
                    float2 f = unpk(s2);
                    float sval = f.x + f.y;
                    int d = dd[tt];
                    if (d == curd) cur += sval;
                    else {
                        if (curd >= 0) atomicAdd(out + curd * 16 + o, cur);
                        curd = d; cur = sval;
                    }
                }
            }
            if (curd >= 0) atomicAdd(out + curd * 16 + o, cur);
        }
        __syncthreads();
    }
}

// ---------------------------------------------------------------------------
// finalize: divide by degree (or zero)
// ---------------------------------------------------------------------------
__global__ void __launch_bounds__(256)
finalize_kernel(const float* __restrict__ degs, float* __restrict__ out)
{
    int idx = blockIdx.x * blockDim.x + threadIdx.x;
    if (idx >= N_NODES * 16) return;
    float d = degs[idx >> 4];
    float v = out[idx];
    out[idx] = (d > 0.f) ? v / d : 0.f;
}

// ---------------------------------------------------------------------------
extern "C" void kernel_launch(void* const* d_in, const int* in_sizes, int n_in,
                              void* d_out, int out_size)
{
    const float* x    = (const float*)d_in[0];   // [N, 16]
    const float* ef   = (const float*)d_in[1];   // [E, 13]
    const float* W1   = (const float*)d_in[2];   // [13, 32]
    const float* b1   = (const float*)d_in[3];   // [32]
    const float* W2   = (const float*)d_in[4];   // [32, 256]
    const float* b2   = (const float*)d_in[5];   // [256]
    const int*   idxn = (const int*)d_in[6];     // [E]
    const int*   idxd = (const int*)d_in[7];     // [E]
    const float* degs = (const float*)d_in[8];   // [N]
    float* out = (float*)d_out;                  // [N, 16]

    const int E = in_sizes[6];
    const int nChunks = (E + TB - 1) / TB;

    const int n4 = (N_NODES * 16) / 4;
    zero_kernel<<<(n4 + 255) / 256, 256>>>((float4*)out, n4);

    phase1_kernel<<<592, THREADS>>>(x, ef, W1, b1, W2, b2, idxn, idxd, out, E, nChunks);

    finalize_kernel<<<(N_NODES * 16 + 255) / 256, 256>>>(degs, out);
}

// round 3
// speedup vs baseline: 1.7194x; 1.3301x over previous
#include <cuda_runtime.h>

#define N_NODES 50000
#define IN_C   16
#define OUT_C  16
#define EDGE_F 13
#define HID    32
#define NB     8      // nodes per edge-pass block
#define CH     64     // edges per staging chunk
#define NBK    16     // nodes per node-pass block

typedef unsigned long long ull;

// M[n][j*8+p] : packed (i=2p, 2p+1) accumulators of sum_e h_j * x_i  (102.4 MB)
__device__ ull Mg[(size_t)N_NODES * 256];
// S[n][p]     : packed sum_e x_i pairs (for the b2 term)               (3.2 MB)
__device__ ull Sg[(size_t)N_NODES * 8];

// ---- packed fp32x2 helpers (sm_103a FFMA2, PTX-only) ----
__device__ __forceinline__ ull pk2(float a, float b) {
    ull r; asm("mov.b64 %0, {%1,%2};" : "=l"(r) : "f"(a), "f"(b)); return r;
}
__device__ __forceinline__ ull ffma2(ull a, ull b, ull c) {
    ull d; asm("fma.rn.f32x2 %0, %1, %2, %3;" : "=l"(d) : "l"(a), "l"(b), "l"(c)); return d;
}
__device__ __forceinline__ ull add2(ull a, ull b) {
    ull d; asm("add.rn.f32x2 %0, %1, %2;" : "=l"(d) : "l"(a), "l"(b)); return d;
}
__device__ __forceinline__ float2 unpk(ull a) {
    float2 f; asm("mov.b64 {%0,%1}, %2;" : "=f"(f.x), "=f"(f.y) : "l"(a)); return f;
}

// ---------------------------------------------------------------------------
// Edge pass: M[n,j,i] += h[e,j]*x[src,i] ; S[n,i] += x[src,i]
// Block owns nodes [b*NB, b*NB+NB): all their edges are contiguous in idxd
// (sorted), found by binary search. Thread owns one (j, i-pair) slot of M in
// a register; flush = plain coalesced STG at each node boundary. No atomics.
// ---------------------------------------------------------------------------
__global__ void __launch_bounds__(256)
edge_kernel(const float* __restrict__ x,
            const float* __restrict__ ef,
            const float* __restrict__ W1,
            const float* __restrict__ b1,
            const int*   __restrict__ idxn,
            const int*   __restrict__ idxd,
            int E)
{
    __shared__ float W1s[EDGE_F][HID];
    __shared__ float b1s[HID];
    __shared__ float EFs[CH][EDGE_F];
    __shared__ ull   hT2[HID][CH + 1];   // packed {h,h}, padded -> conflict-free
    __shared__ ull   xs2[CH][8];         // packed x pairs of src row
    __shared__ int   dsts[CH + 1];       // staged idxd + 1 lookahead
    __shared__ int   srange[2];

    const int tid = threadIdx.x;

    for (int k = tid; k < EDGE_F * HID; k += 256)
        W1s[k / HID][k % HID] = W1[k];
    if (tid < HID) b1s[tid] = b1[tid];

    const int nbase = blockIdx.x * NB;
    if (tid < 2) {
        int target = nbase + tid * NB;
        if (target > N_NODES) target = N_NODES;
        int lo = 0, hi = E;
        while (lo < hi) {
            int mid = (lo + hi) >> 1;
            if (idxd[mid] < target) lo = mid + 1; else hi = mid;
        }
        srange[tid] = lo;
    }
    __syncthreads();

    const int es = srange[0], ee = srange[1];
    const int j = tid >> 3;     // 0..31
    const int p = tid & 7;      // 0..7
    const bool sthread = (tid < 8);   // these 8 also accumulate S

    ull acc  = 0ULL;
    ull accS = 0ULL;

    for (int base = es; base < ee; base += CH) {
        const int c = min(CH, ee - base);

        // stage destination ids (+1 lookahead)
        if (tid <= c) {
            int gi = base + tid;
            dsts[tid] = (gi < E) ? idxd[gi] : -1;
        }
        // stage edgefeats (coalesced)
        for (int k = tid; k < c * EDGE_F; k += 256)
            EFs[k / EDGE_F][k % EDGE_F] = ef[base * EDGE_F + k];
        // stage x[src] rows as packed pairs (gather, x is 3.2MB -> L2-hot)
        if (tid < c * 4) {
            int e = tid >> 2, q = tid & 3;
            int src = idxn[base + e];
            float4 v = __ldg((const float4*)x + (size_t)src * 4 + q);
            ((float4*)&xs2[e][0])[q] = v;
        }
        __syncthreads();

        // h[e,j] = relu(ef[e] @ W1[:,j] + b1[j]), stored packed {h,h}
        for (int k = tid; k < c * HID; k += 256) {
            int e = k >> 5, jj = k & 31;
            float hh = b1s[jj];
            #pragma unroll
            for (int f = 0; f < EDGE_F; f++)
                hh = fmaf(EFs[e][f], W1s[f][jj], hh);
            hh = fmaxf(hh, 0.f);
            hT2[jj][e] = pk2(hh, hh);
        }
        __syncthreads();

        // rank-1 accumulate + boundary flush (uniform branch; sorted idxd)
        #pragma unroll 4
        for (int e = 0; e < c; e++) {
            ull x2 = xs2[e][p];
            acc = ffma2(hT2[j][e], x2, acc);
            if (sthread) accS = add2(accS, x2);
            int d = dsts[e];
            if (dsts[e + 1] != d) {           // last edge of node d
                Mg[(size_t)d * 256 + tid] = acc;
                acc = 0ULL;
                if (sthread) { Sg[(size_t)d * 8 + p] = accS; accS = 0ULL; }
            }
        }
        __syncthreads();
    }
}

// ---------------------------------------------------------------------------
// Node pass: out[n,o] = ( sum_{j,i} M[n,j,i] W2[j,i*16+o] + sum_i S[n,i] b2[i*16+o] ) / deg
// 16 nodes per block, thread = (node, o). K=512 split in two halves so
// M tile + W2 tile fit smem. All LDS broadcast/spread verified conflict-free.
// ---------------------------------------------------------------------------
__global__ void __launch_bounds__(256)
node_kernel(const float* __restrict__ W2,
            const float* __restrict__ b2,
            const float* __restrict__ degs,
            float* __restrict__ out)
{
    __shared__ ull W2h[128 * 16];    // [k][o] for current half (16 KB)
    __shared__ ull Mh[NBK * 129];    // [node][k] padded (16.1 KB)
    __shared__ ull S2s[NBK * 9];     // padded
    __shared__ ull b2q[8 * 16];      // [p][o]

    const int tid = threadIdx.x;
    const int nbase = blockIdx.x * NBK;
    const int nl = tid >> 4, o = tid & 15;
    const int n = nbase + nl;

    if (tid < 128) {
        int pp = tid >> 4, oo = tid & 15;
        b2q[pp * 16 + oo] = pk2(__ldg(b2 + (2 * pp) * 16 + oo),
                                __ldg(b2 + (2 * pp + 1) * 16 + oo));
    }
    if (tid < NBK * 8) {
        int n_l = tid >> 3, pp = tid & 7;
        int nn = nbase + n_l;
        S2s[n_l * 9 + pp] = (nn < N_NODES) ? Sg[(size_t)nn * 8 + pp] : 0ULL;
    }

    ull s2 = 0ULL;
    #pragma unroll
    for (int half = 0; half < 2; half++) {
        // stage W2 half: [k = (j-16*half)*8+p][o] packed over i-pairs
        for (int idx = tid; idx < 128 * 32; idx += 256) {
            int k = idx >> 5, rem = idx & 31;
            int oo = rem >> 1, hl = rem & 1;
            int jj = half * 16 + (k >> 3), pp = k & 7;
            ((float*)W2h)[k * 32 + oo * 2 + hl] = W2[jj * 256 + (2 * pp + hl) * 16 + oo];
        }
        // stage M half (coalesced ull loads)
        for (int idx = tid; idx < NBK * 128; idx += 256) {
            int n_l = idx >> 7, kk = idx & 127;
            int nn = nbase + n_l;
            Mh[n_l * 129 + kk] = (nn < N_NODES) ? Mg[(size_t)nn * 256 + half * 128 + kk]
                                                : 0ULL;
        }
        __syncthreads();

        #pragma unroll 8
        for (int kk = 0; kk < 128; kk++)
            s2 = ffma2(Mh[nl * 129 + kk], W2h[kk * 16 + o], s2);
        __syncthreads();
    }

    // b2 term via S
    #pragma unroll
    for (int pp = 0; pp < 8; pp++)
        s2 = ffma2(S2s[nl * 9 + pp], b2q[pp * 16 + o], s2);

    if (n < N_NODES) {
        float2 f = unpk(s2);
        float d = degs[n];
        out[n * 16 + o] = (d > 0.f) ? (f.x + f.y) / d : 0.f;
    }
}

// ---------------------------------------------------------------------------
extern "C" void kernel_launch(void* const* d_in, const int* in_sizes, int n_in,
                              void* d_out, int out_size)
{
    const float* x    = (const float*)d_in[0];   // [N, 16]
    const float* ef   = (const float*)d_in[1];   // [E, 13]
    const float* W1   = (const float*)d_in[2];   // [13, 32]
    const float* b1   = (const float*)d_in[3];   // [32]
    const float* W2   = (const float*)d_in[4];   // [32, 256]
    const float* b2   = (const float*)d_in[5];   // [256]
    const int*   idxn = (const int*)d_in[6];     // [E]
    const int*   idxd = (const int*)d_in[7];     // [E]
    const float* degs = (const float*)d_in[8];   // [N]
    float* out = (float*)d_out;                  // [N, 16]

    const int E = in_sizes[6];

    edge_kernel<<<(N_NODES + NB - 1) / NB, 256>>>(x, ef, W1, b1, idxn, idxd, E);
    node_kernel<<<(N_NODES + NBK - 1) / NBK, 256>>>(W2, b2, degs, out);
}

// round 4
// speedup vs baseline: 1.7760x; 1.0329x over previous
#include <cuda_runtime.h>

#define N_NODES 50000
#define EDGE_F  13
#define HID     32
#define NB      4            // nodes per main edge-block
#define CHE     128          // edges per staging chunk
#define PAIRS   64           // CHE/2
#define EX      64           // dedicated blocks for node 0
#define NBLK    ((N_NODES + NB - 1) / NB)   // 12500
#define NBK     64           // nodes per node-pass block
#define KC      32           // ull K-slots per piece (8 pieces of K=256)

typedef unsigned long long ull;

// M[n][j*8+p] packed over i-pairs {2p,2p+1}  (102.4 MB)
__device__ ull Mg[(size_t)N_NODES * 256];
// S[n][i] as floats (ull-aligned, read as i-pairs by node pass)
__device__ ull Sg[(size_t)N_NODES * 8];

// ---- packed fp32x2 helpers (sm_103a FFMA2, PTX-only) ----
__device__ __forceinline__ ull pk2(float a, float b) {
    ull r; asm("mov.b64 %0, {%1,%2};" : "=l"(r) : "f"(a), "f"(b)); return r;
}
__device__ __forceinline__ ull ffma2(ull a, ull b, ull c) {
    ull d; asm("fma.rn.f32x2 %0, %1, %2, %3;" : "=l"(d) : "l"(a), "l"(b), "l"(c)); return d;
}
__device__ __forceinline__ ull add2(ull a, ull b) {
    ull d; asm("add.rn.f32x2 %0, %1, %2;" : "=l"(d) : "l"(a), "l"(b)); return d;
}
__device__ __forceinline__ float2 unpk(ull a) {
    float2 f; asm("mov.b64 {%0,%1}, %2;" : "=f"(f.x), "=f"(f.y) : "l"(a)); return f;
}

// zero Mg row 0 + Sg row 0 (atomic target for node-0 partials)
__global__ void zero0_kernel()
{
    int t = threadIdx.x;
    Mg[t] = 0ull;                // 256 ull
    if (t < 8) Sg[t] = 0ull;
}

// ---------------------------------------------------------------------------
// Edge pass. acc[j][i] packed {even-local-edge sum, odd sum}.
// Main blocks: 4 nodes (node 0 excluded), boundaries via binary search,
// masked peeled pairs. Extra blocks: stride over node-0 chunks, atomic flush.
// ---------------------------------------------------------------------------
__global__ void __launch_bounds__(256)
edge_kernel(const float* __restrict__ x,
            const float* __restrict__ ef,
            const float* __restrict__ W1,
            const float* __restrict__ b1,
            const int*   __restrict__ idxn,
            const int*   __restrict__ idxd,
            int E)
{
    __shared__ ull EFp[EDGE_F][PAIRS + 1];   // float view [13][130]
    __shared__ ull Xp[16][PAIRS + 1];        // float view [16][130]
    __shared__ ull Hp[HID][PAIRS + 1];       // packed {h(2q), h(2q+1)}
    __shared__ int sb[NB + 1];

    const int tid = threadIdx.x;
    const int bx  = blockIdx.x;
    const int j   = tid >> 3;      // M-slot row  (0..31)
    const int p   = tid & 7;       // M-slot i-pair (0..7)
    const int jj  = tid & 31;      // h-compute column (loop-invariant)

    // W1 column in registers, packed {w,w}
    ull W1r[EDGE_F], b1r;
    #pragma unroll
    for (int f = 0; f < EDGE_F; f++) {
        float w = __ldg(W1 + f * HID + jj);
        W1r[f] = pk2(w, w);
    }
    { float bb = __ldg(b1 + jj); b1r = pk2(bb, bb); }

    const bool is_main = (bx < NBLK);
    int t0 = 0, nn = 0;
    if (is_main) {
        t0 = (bx == 0) ? 1 : bx * NB;
        int t1 = bx * NB + NB; if (t1 > N_NODES) t1 = N_NODES;
        nn = t1 - t0;
        if (tid <= nn) {
            int target = t0 + tid;
            int lo = 0, hi = E;
            while (lo < hi) { int m = (lo + hi) >> 1;
                              if (idxd[m] < target) lo = m + 1; else hi = m; }
            sb[tid] = lo;
        }
    } else {
        if (tid == 0) {
            int lo = 0, hi = E;
            while (lo < hi) { int m = (lo + hi) >> 1;
                              if (idxd[m] < 1) lo = m + 1; else hi = m; }
            sb[0] = lo;           // end of node 0's edges
        }
    }
    __syncthreads();

    ull acc_a = 0ull, acc_b = 0ull, accS = 0ull;
    float* EFf = (float*)EFp;
    float* Xf  = (float*)Xp;
    const ull* hrow = Hp[j];
    const ull* xa   = Xp[2 * p];
    const ull* xb   = Xp[2 * p + 1];

    if (is_main) {
        const int es = sb[0], ee = sb[nn];
        for (int base = es; base < ee; base += CHE) {
            const int c = min(CHE, ee - base);
            const int cpad = (c + 1) & ~1;
            const int qn = cpad >> 1;

            // ---- stage ef (zero-padded), transposed-pair layout ----
            for (int k = tid; k < cpad * EDGE_F; k += 256) {
                int e = k / EDGE_F;
                int f = k - e * EDGE_F;
                EFf[f * 130 + e] = (e < c) ? __ldg(ef + (size_t)base * EDGE_F + k) : 0.f;
            }
            // ---- stage x rows (gather), transposed ----
            for (int t = tid; t < cpad * 4; t += 256) {
                int e = t >> 2, r = t & 3;
                float4 v = make_float4(0.f, 0.f, 0.f, 0.f);
                if (e < c) {
                    int src = __ldg(idxn + base + e);
                    v = __ldg((const float4*)x + (size_t)src * 4 + r);
                }
                Xf[(r * 4 + 0) * 130 + e] = v.x;
                Xf[(r * 4 + 1) * 130 + e] = v.y;
                Xf[(r * 4 + 2) * 130 + e] = v.z;
                Xf[(r * 4 + 3) * 130 + e] = v.w;
            }
            __syncthreads();

            // ---- h pairs: 13 FFMA2 per 2 h-values, W1 in regs ----
            for (int t = tid; t < (qn << 5); t += 256) {
                int q = t >> 5;
                ull h2 = b1r;
                #pragma unroll
                for (int f = 0; f < EDGE_F; f++)
                    h2 = ffma2(EFp[f][q], W1r[f], h2);
                float2 hf = unpk(h2);
                Hp[jj][q] = pk2(fmaxf(hf.x, 0.f), fmaxf(hf.y, 0.f));
            }
            __syncthreads();

            // ---- per-node masked segments (block-uniform bounds) ----
            const int cend = base + c;
            for (int k = 0; k < nn; k++) {
                const int ak = sb[k], bk = sb[k + 1];
                int aL = ak - base; if (aL < 0) aL = 0;
                int bL = bk - base; if (bL > c) bL = c;
                if (bL > aL) {
                    const int qs = aL >> 1, qe = (bL - 1) >> 1;
                    const ull mlo = (aL & 1) ? 0xFFFFFFFF00000000ull : ~0ull;
                    const ull mhi = (bL & 1) ? 0x00000000FFFFFFFFull : ~0ull;
                    ull h2 = hrow[qs] & mlo;
                    if (qe == qs) h2 &= mhi;
                    acc_a = ffma2(h2, xa[qs], acc_a);
                    acc_b = ffma2(h2, xb[qs], acc_b);
                    #pragma unroll 2
                    for (int q = qs + 1; q < qe; q++) {
                        h2 = hrow[q];
                        acc_a = ffma2(h2, xa[q], acc_a);
                        acc_b = ffma2(h2, xb[q], acc_b);
                    }
                    if (qe > qs) {
                        h2 = hrow[qe] & mhi;
                        acc_a = ffma2(h2, xa[qe], acc_a);
                        acc_b = ffma2(h2, xb[qe], acc_b);
                    }
                    if (tid < 16) {   // S accumulation (warp 0, masks on x)
                        const ull* xr = Xp[tid];
                        ull x2 = xr[qs] & mlo;
                        if (qe == qs) x2 &= mhi;
                        accS = add2(accS, x2);
                        for (int q = qs + 1; q < qe; q++) accS = add2(accS, xr[q]);
                        if (qe > qs) accS = add2(accS, xr[qe] & mhi);
                    }
                }
                if (bk <= cend && bk > ak) {       // node complete -> flush
                    float2 fa = unpk(acc_a), fb = unpk(acc_b);
                    Mg[(size_t)(t0 + k) * 256 + tid] = pk2(fa.x + fa.y, fb.x + fb.y);
                    acc_a = 0ull; acc_b = 0ull;
                    if (tid < 16) {
                        float2 fs = unpk(accS);
                        ((float*)Sg)[(size_t)(t0 + k) * 16 + tid] = fs.x + fs.y;
                        accS = 0ull;
                    }
                }
            }
            __syncthreads();
        }
    } else {
        // ---- node-0 slice blocks ----
        const int e0 = sb[0];
        const int ex = bx - NBLK;
        const int nch = (e0 + CHE - 1) / CHE;
        for (int chq = ex; chq < nch; chq += EX) {
            const int base = chq * CHE;
            const int c = min(CHE, e0 - base);
            const int cpad = (c + 1) & ~1;
            const int qn = cpad >> 1;

            for (int k = tid; k < cpad * EDGE_F; k += 256) {
                int e = k / EDGE_F;
                int f = k - e * EDGE_F;
                EFf[f * 130 + e] = (e < c) ? __ldg(ef + (size_t)base * EDGE_F + k) : 0.f;
            }
            for (int t = tid; t < cpad * 4; t += 256) {
                int e = t >> 2, r = t & 3;
                float4 v = make_float4(0.f, 0.f, 0.f, 0.f);
                if (e < c) {
                    int src = __ldg(idxn + base + e);
                    v = __ldg((const float4*)x + (size_t)src * 4 + r);
                }
                Xf[(r * 4 + 0) * 130 + e] = v.x;
                Xf[(r * 4 + 1) * 130 + e] = v.y;
                Xf[(r * 4 + 2) * 130 + e] = v.z;
                Xf[(r * 4 + 3) * 130 + e] = v.w;
            }
            __syncthreads();

            for (int t = tid; t < (qn << 5); t += 256) {
                int q = t >> 5;
                ull h2 = b1r;
                #pragma unroll
                for (int f = 0; f < EDGE_F; f++)
                    h2 = ffma2(EFp[f][q], W1r[f], h2);
                float2 hf = unpk(h2);
                Hp[jj][q] = pk2(fmaxf(hf.x, 0.f), fmaxf(hf.y, 0.f));
            }
            __syncthreads();

            // no masks needed: pad edges zero-filled (x=0)
            #pragma unroll 2
            for (int q = 0; q < qn; q++) {
                ull h2 = hrow[q];
                acc_a = ffma2(h2, xa[q], acc_a);
                acc_b = ffma2(h2, xb[q], acc_b);
            }
            if (tid < 16) {
                const ull* xr = Xp[tid];
                for (int q = 0; q < qn; q++) accS = add2(accS, xr[q]);
            }
            __syncthreads();
        }
        // one atomic flush per extra block onto pre-zeroed row 0
        float2 fa = unpk(acc_a), fb = unpk(acc_b);
        float* Mf = (float*)&Mg[0];
        atomicAdd(Mf + tid * 2,     fa.x + fa.y);
        atomicAdd(Mf + tid * 2 + 1, fb.x + fb.y);
        if (tid < 16) {
            float2 fs = unpk(accS);
            atomicAdd((float*)Sg + tid, fs.x + fs.y);
        }
    }
}

// ---------------------------------------------------------------------------
// Node pass: out[n,o] = (sum_k M[n,k]·W2q[k,o] + sum_i S[n,i] b2[i,o]) / deg
// 64 nodes/block, thread = (node-quad, o): 4 outputs/thread, K in 8 pieces.
// ---------------------------------------------------------------------------
__global__ void __launch_bounds__(256)
node_kernel(const float* __restrict__ W2,
            const float* __restrict__ b2,
            const float* __restrict__ degs,
            float* __restrict__ out)
{
    __shared__ ull W2c[KC][16];
    __shared__ ull Mc[NBK][KC + 1];
    __shared__ ull S2s[NBK][8];
    __shared__ ull b2q[8][16];

    const int tid = threadIdx.x;
    const int g = tid >> 4;        // node quad 0..15
    const int o = tid & 15;
    const int nbase = blockIdx.x * NBK;

    if (tid < 128) {
        int pp = tid >> 4, oo = tid & 15;
        b2q[pp][oo] = pk2(__ldg(b2 + 2 * pp * 16 + oo),
                          __ldg(b2 + (2 * pp + 1) * 16 + oo));
    }
    for (int t = tid; t < NBK * 8; t += 256) {
        int nl = t >> 3, pp = t & 7;
        int n = nbase + nl;
        S2s[nl][pp] = (n < N_NODES) ? Sg[(size_t)n * 8 + pp] : 0ull;
    }

    ull s0 = 0ull, s1 = 0ull, s2 = 0ull, s3 = 0ull;
    const ull* m0 = Mc[g * 4 + 0];
    const ull* m1 = Mc[g * 4 + 1];
    const ull* m2 = Mc[g * 4 + 2];
    const ull* m3 = Mc[g * 4 + 3];

    #pragma unroll 1
    for (int piece = 0; piece < 8; piece++) {
        for (int t = tid; t < KC * 32; t += 256) {      // W2 piece (1024 floats)
            int kk = t >> 5, rr = t & 31;
            int oo = rr >> 1, hl = rr & 1;
            int kg = piece * KC + kk;
            int jw = kg >> 3, pw = kg & 7;
            ((float*)&W2c[kk][oo])[hl] = __ldg(W2 + jw * 256 + (2 * pw + hl) * 16 + oo);
        }
        for (int t = tid; t < NBK * KC; t += 256) {     // M piece (coalesced)
            int nl = t >> 5, kk = t & 31;
            int n = nbase + nl;
            Mc[nl][kk] = (n < N_NODES) ? Mg[(size_t)n * 256 + piece * KC + kk] : 0ull;
        }
        __syncthreads();

        #pragma unroll 8
        for (int kk = 0; kk < KC; kk++) {
            ull w = W2c[kk][o];
            s0 = ffma2(m0[kk], w, s0);
            s1 = ffma2(m1[kk], w, s1);
            s2 = ffma2(m2[kk], w, s2);
            s3 = ffma2(m3[kk], w, s3);
        }
        __syncthreads();
    }

    #pragma unroll
    for (int t = 0; t < 4; t++) {
        int n = nbase + g * 4 + t;
        if (n < N_NODES) {
            ull s = (t == 0) ? s0 : (t == 1) ? s1 : (t == 2) ? s2 : s3;
            #pragma unroll
            for (int pp = 0; pp < 8; pp++)
                s = ffma2(S2s[g * 4 + t][pp], b2q[pp][o], s);
            float2 f = unpk(s);
            float d = __ldg(degs + n);
            out[n * 16 + o] = (d > 0.f) ? (f.x + f.y) / d : 0.f;
        }
    }
}

// ---------------------------------------------------------------------------
extern "C" void kernel_launch(void* const* d_in, const int* in_sizes, int n_in,
                              void* d_out, int out_size)
{
    const float* x    = (const float*)d_in[0];   // [N, 16]
    const float* ef   = (const float*)d_in[1];   // [E, 13]
    const float* W1   = (const float*)d_in[2];   // [13, 32]
    const float* b1   = (const float*)d_in[3];   // [32]
    const float* W2   = (const float*)d_in[4];   // [32, 256]
    const float* b2   = (const float*)d_in[5];   // [256]
    const int*   idxn = (const int*)d_in[6];     // [E]
    const int*   idxd = (const int*)d_in[7];     // [E]
    const float* degs = (const float*)d_in[8];   // [N]
    float* out = (float*)d_out;                  // [N, 16]

    const int E = in_sizes[6];

    zero0_kernel<<<1, 256>>>();
    edge_kernel<<<NBLK + EX, 256>>>(x, ef, W1, b1, idxn, idxd, E);
    node_kernel<<<(N_NODES + NBK - 1) / NBK, 256>>>(W2, b2, degs, out);
}